// round 16
// baseline (speedup 1.0000x reference)
#include <cuda_runtime.h>

// result = 2*(C-1)/C^2 * mean(|ct|)  with C=8, H=W=512.
// Per pixel with target t, argmax q, value v:
//   sum_{c,l} |v*[l==t] - v*[c==q]| = 2*(C-1)*|v|, independent of t and q.
// pred_stage1 / target are never read; this is an abs-mean of ct (1 MB).
//
// Two kernels with PDL overlap (best-measured structure):
//  - stage1: 64 CTAs x 512 thr, 2 independent float4 loads/thread; publishes
//    its partial, fences, and fires cudaTriggerProgrammaticLaunchCompletion()
//    so stage2's grid-dependency wait releases the moment the last partial
//    lands. Stage2's dispatch overlaps stage1's execution entirely.
//  - stage2: ONE warp; each lane reads 2 partials in fixed order, 5-step
//    shfl tree, scale, STG. Minimal tail.
// Fixed summation order everywhere -> bit-deterministic across replays.

#define S1_BLOCKS  64
#define S1_THREADS 512
#define S1_WARPS   (S1_THREADS / 32)

__device__ float g_partials[S1_BLOCKS];

__global__ void __launch_bounds__(S1_THREADS)
abs_sum_stage1(const float4* __restrict__ ct4) {
    // 65536 float4s -> 64*512*2: 2 per thread, coalesced, independent (MLP=2)
    int base = blockIdx.x * (S1_THREADS * 2) + threadIdx.x;
    float4 a = ct4[base];
    float4 b = ct4[base + S1_THREADS];
    float s = (fabsf(a.x) + fabsf(a.y)) + (fabsf(a.z) + fabsf(a.w))
            + (fabsf(b.x) + fabsf(b.y)) + (fabsf(b.z) + fabsf(b.w));

    #pragma unroll
    for (int o = 16; o > 0; o >>= 1)
        s += __shfl_xor_sync(0xffffffffu, s, o);

    __shared__ float ws[S1_WARPS];
    if ((threadIdx.x & 31) == 0) ws[threadIdx.x >> 5] = s;
    __syncthreads();

    if (threadIdx.x == 0) {
        float bs = (((ws[0]  + ws[1])  + (ws[2]  + ws[3]))
                 +  ((ws[4]  + ws[5])  + (ws[6]  + ws[7])))
                 + (((ws[8]  + ws[9])  + (ws[10] + ws[11]))
                 +  ((ws[12] + ws[13]) + (ws[14] + ws[15])));
        g_partials[blockIdx.x] = bs;
        __threadfence();
        cudaTriggerProgrammaticLaunchCompletion();
    }
}

__global__ void __launch_bounds__(32)
abs_sum_stage2(float* __restrict__ out, float scale) {
    cudaGridDependencySynchronize();  // releases when all stage1 blocks trigger

    int t = threadIdx.x;
    // fixed order -> deterministic; partials are L2-hot
    float s = g_partials[t] + g_partials[t + 32];
    #pragma unroll
    for (int o = 16; o > 0; o >>= 1)
        s += __shfl_xor_sync(0xffffffffu, s, o);
    if (t == 0) out[0] = s * scale;
}

extern "C" void kernel_launch(void* const* d_in, const int* in_sizes, int n_in,
                              void* d_out, int out_size) {
    // inputs: [0] pred_stage1 f32 (unused), [1] ct f32, [2] target i64 (unused)
    const float* ct = (const float*)d_in[1];
    int n = in_sizes[1];  // 262144

    const int C = 8;
    float scale = (2.0f * (C - 1)) / ((float)(C * C)) / (float)n;

    abs_sum_stage1<<<S1_BLOCKS, S1_THREADS>>>((const float4*)ct);

    // stage2 with programmatic dependent launch: dispatch overlaps stage1
    cudaLaunchConfig_t cfg = {};
    cfg.gridDim = dim3(1, 1, 1);
    cfg.blockDim = dim3(32, 1, 1);
    cfg.dynamicSmemBytes = 0;
    cfg.stream = 0;
    cudaLaunchAttribute attr[1];
    attr[0].id = cudaLaunchAttributeProgrammaticStreamSerialization;
    attr[0].val.programmaticStreamSerializationAllowed = 1;
    cfg.attrs = attr;
    cfg.numAttrs = 1;
    cudaLaunchKernelEx(&cfg, abs_sum_stage2, (float*)d_out, scale);
}